// round 1
// baseline (speedup 1.0000x reference)
#include <cuda_runtime.h>
#include <cuda_bf16.h>
#include <math.h>

// Problem constants
#define TT 512
#define BB 64
#define II 300
#define HH 1000
#define G4 4000   // 4*H

// ---------------------------------------------------------------------------
// Device scratch (allocation-free: __device__ globals, loader-backed)
// ---------------------------------------------------------------------------
__device__ float g_xg[(size_t)TT * BB * G4];  // precomputed input gates [T,B,4H] (512 MB, bss)
__device__ float g_c[BB * HH];                // cell state [B,H]

// ---------------------------------------------------------------------------
// tf32 helpers
// ---------------------------------------------------------------------------
__device__ __forceinline__ unsigned f2tf32(float x) {
    unsigned y;
    asm("cvt.rna.tf32.f32 %0, %1;" : "=r"(y) : "f"(x));
    return y;
}

__device__ __forceinline__ void mma_tf32(float c[4], const unsigned a[4],
                                         unsigned b0, unsigned b1) {
    asm volatile(
        "mma.sync.aligned.m16n8k8.row.col.f32.tf32.tf32.f32 "
        "{%0,%1,%2,%3}, {%4,%5,%6,%7}, {%8,%9}, {%0,%1,%2,%3};"
        : "+f"(c[0]), "+f"(c[1]), "+f"(c[2]), "+f"(c[3])
        : "r"(a[0]), "r"(a[1]), "r"(a[2]), "r"(a[3]), "r"(b0), "r"(b1));
}

__device__ __forceinline__ float sigmoidf_(float x) {
    return 1.0f / (1.0f + expf(-x));
}

// ---------------------------------------------------------------------------
// Kernel 0: init cell state from c0
// ---------------------------------------------------------------------------
__global__ void init_c_kernel(const float* __restrict__ c0) {
    int i = blockIdx.x * blockDim.x + threadIdx.x;
    if (i < BB * HH) g_c[i] = c0[i];
}

// ---------------------------------------------------------------------------
// Kernel 1: x_gates = inputs @ W_ih^T + (b_ih + b_hh)
//   A = inputs [M=32768, K=300] row-major, B = W_ih [N=4000, K=300] row-major
//   Block tile 64m x 64n, 8 warps (4 m-warps x 2 n-warps of 16x32), kc=16.
// ---------------------------------------------------------------------------
__global__ void __launch_bounds__(256) xgates_kernel(
    const float* __restrict__ X, const float* __restrict__ Wih,
    const float* __restrict__ b_ih, const float* __restrict__ b_hh)
{
    const int m0 = blockIdx.y * 64;
    const int n0 = blockIdx.x * 64;
    const int tid  = threadIdx.x;
    const int lane = tid & 31;
    const int warp = tid >> 5;
    const int wm = warp & 3;   // m-warp: rows wm*16 .. wm*16+15
    const int wn = warp >> 2;  // n-warp: cols wn*32 .. wn*32+31 (4 n8-subtiles)

    __shared__ unsigned a_s[64][17];
    __shared__ unsigned b_s[64][17];

    float acc[4][4];
#pragma unroll
    for (int s = 0; s < 4; ++s)
#pragma unroll
        for (int i = 0; i < 4; ++i) acc[s][i] = 0.0f;

    const int g_id = lane >> 2;   // 0..7
    const int t_id = lane & 3;    // 0..3

    for (int ch = 0; ch < 19; ++ch) {          // 19*16 = 304 >= 300 (zero-padded)
        const int k0 = ch * 16;
        // stage A (64x16) and B (64x16), tf32-rounded
#pragma unroll
        for (int it = 0; it < 4; ++it) {
            int i = tid + it * 256;
            int m = i >> 4, k = i & 15;
            float va = (k0 + k < II) ? X[(size_t)(m0 + m) * II + k0 + k] : 0.0f;
            a_s[m][k] = f2tf32(va);
            int n = m;
            int r = n0 + n;
            float vb = (r < G4 && k0 + k < II) ? Wih[(size_t)r * II + k0 + k] : 0.0f;
            b_s[n][k] = f2tf32(vb);
        }
        __syncthreads();

#pragma unroll
        for (int kk = 0; kk < 2; ++kk) {
            const int kb = kk * 8;
            unsigned a[4];
            a[0] = a_s[wm * 16 + g_id][kb + t_id];
            a[1] = a_s[wm * 16 + g_id + 8][kb + t_id];
            a[2] = a_s[wm * 16 + g_id][kb + t_id + 4];
            a[3] = a_s[wm * 16 + g_id + 8][kb + t_id + 4];
#pragma unroll
            for (int s = 0; s < 4; ++s) {
                unsigned b0 = b_s[wn * 32 + s * 8 + g_id][kb + t_id];
                unsigned b1 = b_s[wn * 32 + s * 8 + g_id][kb + t_id + 4];
                mma_tf32(acc[s], a, b0, b1);
            }
        }
        __syncthreads();
    }

    // epilogue: add bias, store
#pragma unroll
    for (int s = 0; s < 4; ++s) {
        int n = n0 + wn * 32 + s * 8 + 2 * t_id;   // even
        int row = m0 + wm * 16 + g_id;
        if (n < G4) {
            float bia0 = b_ih[n] + b_hh[n];
            float bia1 = b_ih[n + 1] + b_hh[n + 1];
            g_xg[(size_t)row * G4 + n]           = acc[s][0] + bia0;
            g_xg[(size_t)row * G4 + n + 1]       = acc[s][1] + bia1;
            g_xg[(size_t)(row + 8) * G4 + n]     = acc[s][2] + bia0;
            g_xg[(size_t)(row + 8) * G4 + n + 1] = acc[s][3] + bia1;
        }
    }
}

// ---------------------------------------------------------------------------
// Kernel 2: one LSTM step (fused recurrent GEMM + cell update)
//   gates[64, 32cols] = h_prev[64,1000] @ Whh_rows^T   (tf32 MMA, K=1000)
//   Block owns j-slice of 8, gate-major columns: col c -> row (c>>3)*H + j0+(c&7)
//   125 blocks x 256 threads; 8 warps = 4 m-warps x 2 n-warps (16x16 each).
// ---------------------------------------------------------------------------
__global__ void __launch_bounds__(256) lstm_step_kernel(
    int t, const float* __restrict__ h_prev, const float* __restrict__ Whh,
    float* __restrict__ out)
{
    const int j0 = blockIdx.x * 8;
    const int tid  = threadIdx.x;
    const int lane = tid & 31;
    const int warp = tid >> 5;
    const int wm = warp & 3;   // m (=batch) warp
    const int wn = warp >> 2;  // n warp (16 cols each)

    __shared__ unsigned h_s[64][41];   // kc = 40
    __shared__ unsigned w_s[32][41];
    __shared__ float    g_sm[64][33];

    const int g_id = lane >> 2;
    const int t_id = lane & 3;

    float acc[2][4];
#pragma unroll
    for (int s = 0; s < 2; ++s)
#pragma unroll
        for (int i = 0; i < 4; ++i) acc[s][i] = 0.0f;

    for (int ch = 0; ch < 25; ++ch) {          // 25 * 40 = 1000
        const int k0 = ch * 40;
        // stage h (64x40)
#pragma unroll
        for (int it = 0; it < 10; ++it) {
            int i = tid + it * 256;
            int b = i / 40, k = i % 40;
            h_s[b][k] = f2tf32(h_prev[(size_t)b * HH + k0 + k]);
        }
        // stage W rows (32x40), gate-major column mapping
#pragma unroll
        for (int it = 0; it < 5; ++it) {
            int i = tid + it * 256;
            int r = i / 40, k = i % 40;
            int gate = r >> 3;
            int row  = gate * HH + j0 + (r & 7);
            w_s[r][k] = f2tf32(Whh[(size_t)row * HH + k0 + k]);
        }
        __syncthreads();

#pragma unroll
        for (int kk = 0; kk < 5; ++kk) {
            const int kb = kk * 8;
            unsigned a[4];
            a[0] = h_s[wm * 16 + g_id][kb + t_id];
            a[1] = h_s[wm * 16 + g_id + 8][kb + t_id];
            a[2] = h_s[wm * 16 + g_id][kb + t_id + 4];
            a[3] = h_s[wm * 16 + g_id + 8][kb + t_id + 4];
#pragma unroll
            for (int s = 0; s < 2; ++s) {
                unsigned b0 = w_s[wn * 16 + s * 8 + g_id][kb + t_id];
                unsigned b1 = w_s[wn * 16 + s * 8 + g_id][kb + t_id + 4];
                mma_tf32(acc[s], a, b0, b1);
            }
        }
        __syncthreads();
    }

    // spill gates to smem so the cell phase sees all 4 gates per (b, j)
#pragma unroll
    for (int s = 0; s < 2; ++s) {
        int col = wn * 16 + s * 8 + 2 * t_id;
        int row = wm * 16 + g_id;
        g_sm[row][col]         = acc[s][0];
        g_sm[row][col + 1]     = acc[s][1];
        g_sm[row + 8][col]     = acc[s][2];
        g_sm[row + 8][col + 1] = acc[s][3];
    }
    __syncthreads();

    // cell update: 512 elements (64 b x 8 j), 2 per thread
#pragma unroll
    for (int e = tid; e < 512; e += 256) {
        int b  = e >> 3;
        int jj = e & 7;
        int j  = j0 + jj;
        const float* xg = g_xg + ((size_t)t * BB + b) * G4;
        float iv = g_sm[b][jj]          + xg[j];
        float fv = g_sm[b][8 + jj]      + xg[HH + j];
        float gv = g_sm[b][16 + jj]     + xg[2 * HH + j];
        float ov = g_sm[b][24 + jj]     + xg[3 * HH + j];
        iv = sigmoidf_(iv);
        fv = sigmoidf_(fv);
        gv = tanhf(gv);
        ov = sigmoidf_(ov);
        float c_old = g_c[b * HH + j];
        float c_new = fv * c_old + iv * gv;
        float h_new = ov * tanhf(c_new);
        g_c[b * HH + j] = c_new;
        out[((size_t)t * BB + b) * HH + j] = h_new;
    }
}

// ---------------------------------------------------------------------------
// Launch
// ---------------------------------------------------------------------------
extern "C" void kernel_launch(void* const* d_in, const int* in_sizes, int n_in,
                              void* d_out, int out_size) {
    const float* inputs = (const float*)d_in[0];  // [T,B,I]
    const float* h0     = (const float*)d_in[1];  // [B,H]
    const float* c0     = (const float*)d_in[2];  // [B,H]
    const float* W_ih   = (const float*)d_in[3];  // [4H,I]
    const float* W_hh   = (const float*)d_in[4];  // [4H,H]
    const float* b_ih   = (const float*)d_in[5];  // [4H]
    const float* b_hh   = (const float*)d_in[6];  // [4H]
    float* out = (float*)d_out;                   // [T,B,H]

    // 1) cell state init
    init_c_kernel<<<(BB * HH + 255) / 256, 256>>>(c0);

    // 2) input-gate precompute: grid (N-tiles=63, M-tiles=512)
    xgates_kernel<<<dim3(63, 512), 256>>>(inputs, W_ih, b_ih, b_hh);

    // 3) 512 sequential steps; h history lives in `out`
    for (int t = 0; t < TT; ++t) {
        const float* h_prev = (t == 0) ? h0 : (out + (size_t)(t - 1) * BB * HH);
        lstm_step_kernel<<<125, 256>>>(t, h_prev, W_hh, out);
    }
}

// round 2
// speedup vs baseline: 1.5978x; 1.5978x over previous
#include <cuda_runtime.h>
#include <cuda_bf16.h>
#include <math.h>

// Problem constants
#define TT 512
#define BB 64
#define II 300
#define HH 1000
#define G4 4000   // 4*H
#define NBLK 125  // persistent blocks (1 per SM, 125 <= 148)

// ---------------------------------------------------------------------------
// Device scratch (allocation-free: __device__ globals, loader-backed)
// ---------------------------------------------------------------------------
__device__ float g_xg[(size_t)TT * BB * G4];  // precomputed input gates [T,B,4H]
__device__ unsigned g_bar;                    // step barrier counter

// ---------------------------------------------------------------------------
// tf32 helpers
// ---------------------------------------------------------------------------
__device__ __forceinline__ unsigned f2tf32(float x) {
    unsigned y;
    asm("cvt.rna.tf32.f32 %0, %1;" : "=r"(y) : "f"(x));
    return y;
}

__device__ __forceinline__ void mma_tf32(float c[4], const unsigned a[4],
                                         unsigned b0, unsigned b1) {
    asm volatile(
        "mma.sync.aligned.m16n8k8.row.col.f32.tf32.tf32.f32 "
        "{%0,%1,%2,%3}, {%4,%5,%6,%7}, {%8,%9}, {%0,%1,%2,%3};"
        : "+f"(c[0]), "+f"(c[1]), "+f"(c[2]), "+f"(c[3])
        : "r"(a[0]), "r"(a[1]), "r"(a[2]), "r"(a[3]), "r"(b0), "r"(b1));
}

__device__ __forceinline__ float sigmoidf_(float x) {
    return 1.0f / (1.0f + expf(-x));
}

// ---------------------------------------------------------------------------
// Kernel 0: reset step barrier (per launch/replay)
// ---------------------------------------------------------------------------
__global__ void init_kernel() {
    if (threadIdx.x == 0 && blockIdx.x == 0) g_bar = 0u;
}

// ---------------------------------------------------------------------------
// Kernel 1: x_gates = inputs @ W_ih^T + (b_ih + b_hh)   (unchanged, works)
// ---------------------------------------------------------------------------
__global__ void __launch_bounds__(256) xgates_kernel(
    const float* __restrict__ X, const float* __restrict__ Wih,
    const float* __restrict__ b_ih, const float* __restrict__ b_hh)
{
    const int m0 = blockIdx.y * 64;
    const int n0 = blockIdx.x * 64;
    const int tid  = threadIdx.x;
    const int lane = tid & 31;
    const int warp = tid >> 5;
    const int wm = warp & 3;
    const int wn = warp >> 2;

    __shared__ unsigned a_s[64][17];
    __shared__ unsigned b_s[64][17];

    float acc[4][4];
#pragma unroll
    for (int s = 0; s < 4; ++s)
#pragma unroll
        for (int i = 0; i < 4; ++i) acc[s][i] = 0.0f;

    const int g_id = lane >> 2;
    const int t_id = lane & 3;

    for (int ch = 0; ch < 19; ++ch) {
        const int k0 = ch * 16;
#pragma unroll
        for (int it = 0; it < 4; ++it) {
            int i = tid + it * 256;
            int m = i >> 4, k = i & 15;
            float va = (k0 + k < II) ? X[(size_t)(m0 + m) * II + k0 + k] : 0.0f;
            a_s[m][k] = f2tf32(va);
            int r = n0 + m;
            float vb = (r < G4 && k0 + k < II) ? Wih[(size_t)r * II + k0 + k] : 0.0f;
            b_s[m][k] = f2tf32(vb);
        }
        __syncthreads();

#pragma unroll
        for (int kk = 0; kk < 2; ++kk) {
            const int kb = kk * 8;
            unsigned a[4];
            a[0] = a_s[wm * 16 + g_id][kb + t_id];
            a[1] = a_s[wm * 16 + g_id + 8][kb + t_id];
            a[2] = a_s[wm * 16 + g_id][kb + t_id + 4];
            a[3] = a_s[wm * 16 + g_id + 8][kb + t_id + 4];
#pragma unroll
            for (int s = 0; s < 4; ++s) {
                unsigned b0 = b_s[wn * 32 + s * 8 + g_id][kb + t_id];
                unsigned b1 = b_s[wn * 32 + s * 8 + g_id][kb + t_id + 4];
                mma_tf32(acc[s], a, b0, b1);
            }
        }
        __syncthreads();
    }

#pragma unroll
    for (int s = 0; s < 4; ++s) {
        int n = n0 + wn * 32 + s * 8 + 2 * t_id;
        int row = m0 + wm * 16 + g_id;
        if (n < G4) {
            float bia0 = b_ih[n] + b_hh[n];
            float bia1 = b_ih[n + 1] + b_hh[n + 1];
            g_xg[(size_t)row * G4 + n]           = acc[s][0] + bia0;
            g_xg[(size_t)row * G4 + n + 1]       = acc[s][1] + bia1;
            g_xg[(size_t)(row + 8) * G4 + n]     = acc[s][2] + bia0;
            g_xg[(size_t)(row + 8) * G4 + n + 1] = acc[s][3] + bia1;
        }
    }
}

// ---------------------------------------------------------------------------
// Kernel 2: persistent LSTM — all 512 steps in one launch.
//   125 blocks, each owns 8 h-columns (32 gate-rows of W_hh, resident in smem).
//   Per step: tf32 MMA gates = h_prev @ Whh_slice^T, fused cell update,
//   h_t written to out[t], global spin barrier between steps.
//   c lives in registers; x_gates prefetched into registers across the barrier.
// ---------------------------------------------------------------------------
// smem layout (words):
//   W_s  : 32 * 1004                  (stride 1004: 1004%32==12 -> conflict-free)
//   h_s  : 2 * 64 * 44                (stride 44:   44%32==12  -> conflict-free)
//   g_sm : 64 * 33 floats
#define WS_STRIDE 1004
#define HS_STRIDE 44
#define SMEM_WORDS (32 * WS_STRIDE + 2 * 64 * HS_STRIDE + 64 * 33)

__global__ void __launch_bounds__(256) lstm_persistent(
    const float* __restrict__ h0, const float* __restrict__ c0,
    const float* __restrict__ Whh, float* __restrict__ out)
{
    extern __shared__ unsigned sm[];
    unsigned* W_s = sm;                              // [32][1004]
    unsigned* h_s = sm + 32 * WS_STRIDE;             // [2][64][44]
    float*    g_sm = (float*)(sm + 32 * WS_STRIDE + 2 * 64 * HS_STRIDE); // [64][33]

    const int j0   = blockIdx.x * 8;
    const int tid  = threadIdx.x;
    const int lane = tid & 31;
    const int warp = tid >> 5;
    const int wm = warp & 3;       // m(batch)-warp: rows wm*16..+15
    const int wn = warp >> 2;      // n-warp: cols wn*16..+15
    const int g_id = lane >> 2;
    const int t_id = lane & 3;

    // ---- load W_hh slice into smem once (tf32), gate-major columns ----
    for (int idx = tid; idx < 32 * 1000; idx += 256) {
        int r = idx / 1000, k = idx - r * 1000;
        int gate = r >> 3;
        int row  = gate * HH + j0 + (r & 7);
        W_s[r * WS_STRIDE + k] = f2tf32(Whh[(size_t)row * HH + k]);
    }

    // ---- cell state in registers ----
    float c_reg[2];
#pragma unroll
    for (int q = 0; q < 2; ++q) {
        int e = tid + q * 256;
        int b = e >> 3, jj = e & 7;
        c_reg[q] = c0[b * HH + j0 + jj];
    }

    // ---- prefetch x_gates for t=0 ----
    float xg[2][4];
#pragma unroll
    for (int q = 0; q < 2; ++q) {
        int e = tid + q * 256;
        int b = e >> 3, jj = e & 7;
        const float* p = g_xg + (size_t)b * G4 + j0 + jj;
#pragma unroll
        for (int g = 0; g < 4; ++g) xg[q][g] = p[g * HH];
    }

    __syncthreads();

    // h staging assignment: thread -> (row hb, 10 consecutive k at hk)
    const int hb = tid >> 2;
    const int hk = (tid & 3) * 10;

    for (int t = 0; t < TT; ++t) {
        // ---- wait for h_{t-1} from all blocks ----
        if (t > 0) {
            if (tid == 0) {
                unsigned target = (unsigned)(NBLK * t);
                while (*(volatile unsigned*)&g_bar < target) { }
            }
            __syncthreads();
            __threadfence();
        }
        const float* hp = (t == 0) ? h0 : out + (size_t)(t - 1) * BB * HH;

        float acc[2][4];
#pragma unroll
        for (int s = 0; s < 2; ++s)
#pragma unroll
            for (int i = 0; i < 4; ++i) acc[s][i] = 0.0f;

        // ---- prologue: stage chunk 0 ----
        float r0[10];
#pragma unroll
        for (int j = 0; j < 10; ++j) r0[j] = hp[(size_t)hb * HH + hk + j];
#pragma unroll
        for (int j = 0; j < 10; ++j) h_s[hb * HS_STRIDE + hk + j] = f2tf32(r0[j]);
        __syncthreads();

        // ---- K loop: 25 chunks of 40, double-buffered ----
        for (int ch = 0; ch < 25; ++ch) {
            const int k0  = ch * 40;
            const int cur = (ch & 1) * 64 * HS_STRIDE;

            if (ch < 24) {
#pragma unroll
                for (int j = 0; j < 10; ++j)
                    r0[j] = hp[(size_t)hb * HH + k0 + 40 + hk + j];
            }

#pragma unroll
            for (int kk = 0; kk < 5; ++kk) {
                const int kb = kk * 8;
                unsigned a[4];
                a[0] = h_s[cur + (wm * 16 + g_id) * HS_STRIDE + kb + t_id];
                a[1] = h_s[cur + (wm * 16 + g_id + 8) * HS_STRIDE + kb + t_id];
                a[2] = h_s[cur + (wm * 16 + g_id) * HS_STRIDE + kb + t_id + 4];
                a[3] = h_s[cur + (wm * 16 + g_id + 8) * HS_STRIDE + kb + t_id + 4];
#pragma unroll
                for (int s = 0; s < 2; ++s) {
                    unsigned b0 = W_s[(wn * 16 + s * 8 + g_id) * WS_STRIDE + k0 + kb + t_id];
                    unsigned b1 = W_s[(wn * 16 + s * 8 + g_id) * WS_STRIDE + k0 + kb + t_id + 4];
                    mma_tf32(acc[s], a, b0, b1);
                }
            }
            __syncthreads();
            if (ch < 24) {
                const int nxt = ((ch + 1) & 1) * 64 * HS_STRIDE;
#pragma unroll
                for (int j = 0; j < 10; ++j)
                    h_s[nxt + hb * HS_STRIDE + hk + j] = f2tf32(r0[j]);
                __syncthreads();
            }
        }

        // ---- accumulators -> smem (reshuffle for cell layout) ----
#pragma unroll
        for (int s = 0; s < 2; ++s) {
            int col = wn * 16 + s * 8 + 2 * t_id;
            int row = wm * 16 + g_id;
            g_sm[row * 33 + col]           = acc[s][0];
            g_sm[row * 33 + col + 1]       = acc[s][1];
            g_sm[(row + 8) * 33 + col]     = acc[s][2];
            g_sm[(row + 8) * 33 + col + 1] = acc[s][3];
        }
        __syncthreads();

        // ---- fused cell update ----
#pragma unroll
        for (int q = 0; q < 2; ++q) {
            int e = tid + q * 256;
            int b = e >> 3, jj = e & 7;
            float iv = g_sm[b * 33 + jj]       + xg[q][0];
            float fv = g_sm[b * 33 + 8 + jj]   + xg[q][1];
            float gv = g_sm[b * 33 + 16 + jj]  + xg[q][2];
            float ov = g_sm[b * 33 + 24 + jj]  + xg[q][3];
            iv = sigmoidf_(iv);
            fv = sigmoidf_(fv);
            gv = tanhf(gv);
            ov = sigmoidf_(ov);
            float cn = fv * c_reg[q] + iv * gv;
            c_reg[q] = cn;
            out[((size_t)t * BB + b) * HH + j0 + jj] = ov * tanhf(cn);
        }

        // ---- publish h_t: fence-all, then one arrival per block ----
        __threadfence();
        __syncthreads();
        if (tid == 0) atomicAdd(&g_bar, 1u);

        // ---- prefetch x_gates for t+1 while barrier settles ----
        if (t + 1 < TT) {
#pragma unroll
            for (int q = 0; q < 2; ++q) {
                int e = tid + q * 256;
                int b = e >> 3, jj = e & 7;
                const float* p = g_xg + ((size_t)(t + 1) * BB + b) * G4 + j0 + jj;
#pragma unroll
                for (int g = 0; g < 4; ++g) xg[q][g] = p[g * HH];
            }
        }
        // also prepare next g_sm usage: sync before anyone re-stages h into h_s
        // (the t>0 barrier + syncthreads at loop top provides this)
    }
}

// ---------------------------------------------------------------------------
// Launch
// ---------------------------------------------------------------------------
extern "C" void kernel_launch(void* const* d_in, const int* in_sizes, int n_in,
                              void* d_out, int out_size) {
    const float* inputs = (const float*)d_in[0];  // [T,B,I]
    const float* h0     = (const float*)d_in[1];  // [B,H]
    const float* c0     = (const float*)d_in[2];  // [B,H]
    const float* W_ih   = (const float*)d_in[3];  // [4H,I]
    const float* W_hh   = (const float*)d_in[4];  // [4H,H]
    const float* b_ih   = (const float*)d_in[5];  // [4H]
    const float* b_hh   = (const float*)d_in[6];  // [4H]
    float* out = (float*)d_out;                   // [T,B,H]

    cudaFuncSetAttribute(lstm_persistent,
                         cudaFuncAttributeMaxDynamicSharedMemorySize,
                         SMEM_WORDS * 4);

    init_kernel<<<1, 32>>>();
    xgates_kernel<<<dim3(63, 512), 256>>>(inputs, W_ih, b_ih, b_hh);
    lstm_persistent<<<NBLK, 256, SMEM_WORDS * 4>>>(h0, c0, W_hh, out);
}